// round 2
// baseline (speedup 1.0000x reference)
#include <cuda_runtime.h>
#include <cstdint>
#include <cstddef>

// Problem constants
static constexpr int BATCH = 2;
static constexpr int S_LEN = 2048;
static constexpr int HEADS = 16;
static constexpr int HDIM  = 64;
static constexpr int EMB   = 1024;   // HEADS * HDIM
static constexpr int MROWS = BATCH * S_LEN;   // 4096

static constexpr size_t OUT_ELEMS  = (size_t)BATCH * S_LEN * EMB;                 // 4,194,304
static constexpr size_t ATTN_ELEMS = (size_t)BATCH * HEADS * S_LEN * S_LEN;      // 134,217,728

// Scratch (static device globals — no runtime allocation)
__device__ float g_q [(size_t)BATCH*HEADS*S_LEN*HDIM];   // [B,H,S,Hd]
__device__ float g_k [(size_t)BATCH*HEADS*S_LEN*HDIM];   // [B,H,S,Hd]
__device__ float g_vt[(size_t)BATCH*HEADS*HDIM*S_LEN];   // [B,H,Hd,S]  (V transposed)
__device__ float g_y [(size_t)BATCH*S_LEN*HEADS*HDIM];   // [B,S,H,Hd] == [4096,1024]

enum { MODE_PLAIN = 0, MODE_QK = 1, MODE_VT = 2, MODE_AV = 3 };

// ---------------------------------------------------------------------------
// Generic register-blocked SGEMM:  C = alpha * (A @ B^T) + bias
//   A: [M,K] row-major (lda = K), B: [N,K] row-major (ldb = K)
//   Batched via blockIdx.z with element strides sA, sB, sC.
//   Epilogue "mode" controls the output scatter layout.
// ---------------------------------------------------------------------------
template<int BM, int BN, int BK, int TM, int TN>
__global__ __launch_bounds__((BM/TM)*(BN/TN))
void gemm_kern(const float* __restrict__ A, const float* __restrict__ B,
               const float* __restrict__ bias, float* __restrict__ C,
               int M, int N, int K,
               size_t sA, size_t sB, size_t sC,
               float alpha, int mode)
{
    constexpr int NT = (BM/TM)*(BN/TN);
    __shared__ float As[BK][BM + 4];
    __shared__ float Bs[BK][BN + 4];

    const int tid = threadIdx.x;
    const int z   = blockIdx.z;
    A += (size_t)z * sA;
    B += (size_t)z * sB;
    C += (size_t)z * sC;

    const int row0 = blockIdx.y * BM;
    const int col0 = blockIdx.x * BN;
    const int tx = tid % (BN / TN);
    const int ty = tid / (BN / TN);

    float acc[TM][TN];
#pragma unroll
    for (int i = 0; i < TM; i++)
#pragma unroll
        for (int j = 0; j < TN; j++) acc[i][j] = 0.0f;

    for (int k0 = 0; k0 < K; k0 += BK) {
        // Load A tile (BM x BK), float4 along K, store transposed As[k][m]
#pragma unroll
        for (int l = 0; l < (BM * BK) / (NT * 4); l++) {
            int idx = (tid + l * NT) * 4;
            int r = idx / BK;
            int c = idx % BK;
            float4 v = *reinterpret_cast<const float4*>(A + (size_t)(row0 + r) * K + k0 + c);
            As[c + 0][r] = v.x; As[c + 1][r] = v.y;
            As[c + 2][r] = v.z; As[c + 3][r] = v.w;
        }
        // Load B tile (BN x BK)
#pragma unroll
        for (int l = 0; l < (BN * BK) / (NT * 4); l++) {
            int idx = (tid + l * NT) * 4;
            int r = idx / BK;
            int c = idx % BK;
            float4 v = *reinterpret_cast<const float4*>(B + (size_t)(col0 + r) * K + k0 + c);
            Bs[c + 0][r] = v.x; Bs[c + 1][r] = v.y;
            Bs[c + 2][r] = v.z; Bs[c + 3][r] = v.w;
        }
        __syncthreads();

#pragma unroll
        for (int kk = 0; kk < BK; kk++) {
            float a[TM], b[TN];
#pragma unroll
            for (int i = 0; i < TM; i++) a[i] = As[kk][ty * TM + i];
#pragma unroll
            for (int j = 0; j < TN; j++) b[j] = Bs[kk][tx * TN + j];
#pragma unroll
            for (int i = 0; i < TM; i++)
#pragma unroll
                for (int j = 0; j < TN; j++) acc[i][j] += a[i] * b[j];
        }
        __syncthreads();
    }

    // Epilogue
#pragma unroll
    for (int i = 0; i < TM; i++) {
        const int m = row0 + ty * TM + i;
#pragma unroll
        for (int j = 0; j < TN; j++) {
            const int n = col0 + tx * TN + j;
            float v = acc[i][j] * alpha;
            if (bias) v += bias[n];

            size_t dst;
            if (mode == MODE_PLAIN) {
                dst = (size_t)m * N + n;
            } else if (mode == MODE_QK) {
                // m -> (b,s) over [4096]; n -> (h,hd) over [1024]; out [B,H,S,Hd]
                int b = m >> 11, s = m & 2047;
                int h = n >> 6,  hd = n & 63;
                dst = (((size_t)(b * HEADS + h) * S_LEN + s) * HDIM) + hd;
            } else if (mode == MODE_VT) {
                // out [B,H,Hd,S]
                int b = m >> 11, s = m & 2047;
                int h = n >> 6,  hd = n & 63;
                dst = (((size_t)(b * HEADS + h) * HDIM + hd) * S_LEN) + s;
            } else { // MODE_AV: z = b*HEADS + h; m = q, n = hd; out [B,S,H,Hd]
                int b = z >> 4, h = z & 15;
                dst = (((size_t)(b * S_LEN + m) * HEADS + h) * HDIM) + n;
            }
            C[dst] = v;
        }
    }
}

// ---------------------------------------------------------------------------
// In-place row softmax over rows of length 2048 (one block per row).
// ---------------------------------------------------------------------------
__global__ __launch_bounds__(256)
void softmax_rows(float* __restrict__ attn)
{
    float* row = attn + (size_t)blockIdx.x * S_LEN;
    const int t = threadIdx.x;

    float4 v0 = reinterpret_cast<float4*>(row)[t];
    float4 v1 = reinterpret_cast<float4*>(row)[t + 256];

    float m = fmaxf(fmaxf(fmaxf(v0.x, v0.y), fmaxf(v0.z, v0.w)),
                    fmaxf(fmaxf(v1.x, v1.y), fmaxf(v1.z, v1.w)));

    __shared__ float red[256];
    red[t] = m; __syncthreads();
#pragma unroll
    for (int s = 128; s > 0; s >>= 1) {
        if (t < s) red[t] = fmaxf(red[t], red[t + s]);
        __syncthreads();
    }
    const float M = red[0];
    __syncthreads();

    v0.x = __expf(v0.x - M); v0.y = __expf(v0.y - M);
    v0.z = __expf(v0.z - M); v0.w = __expf(v0.w - M);
    v1.x = __expf(v1.x - M); v1.y = __expf(v1.y - M);
    v1.z = __expf(v1.z - M); v1.w = __expf(v1.w - M);

    float s8 = (v0.x + v0.y + v0.z + v0.w) + (v1.x + v1.y + v1.z + v1.w);
    red[t] = s8; __syncthreads();
#pragma unroll
    for (int s = 128; s > 0; s >>= 1) {
        if (t < s) red[t] += red[t + s];
        __syncthreads();
    }
    const float inv = 1.0f / red[0];

    v0.x *= inv; v0.y *= inv; v0.z *= inv; v0.w *= inv;
    v1.x *= inv; v1.y *= inv; v1.z *= inv; v1.w *= inv;
    reinterpret_cast<float4*>(row)[t]       = v0;
    reinterpret_cast<float4*>(row)[t + 256] = v1;
}

// ---------------------------------------------------------------------------
// Launch
// ---------------------------------------------------------------------------
extern "C" void kernel_launch(void* const* d_in, const int* in_sizes, int n_in,
                              void* d_out, int out_size)
{
    const float* query = (const float*)d_in[0];
    const float* key_i = (const float*)d_in[1];
    const float* value = (const float*)d_in[2];
    const float* q_w   = (const float*)d_in[3];
    const float* q_b   = (const float*)d_in[4];
    const float* k_w   = (const float*)d_in[5];
    const float* k_b   = (const float*)d_in[6];
    const float* v_w   = (const float*)d_in[7];
    const float* v_b   = (const float*)d_in[8];
    const float* o_w   = (const float*)d_in[9];
    const float* o_b   = (const float*)d_in[10];

    float* out  = (float*)d_out;
    float* attn = out + OUT_ELEMS;   // attention occupies the tail of d_out

    float *qp, *kp, *vtp, *yp;
    cudaGetSymbolAddress((void**)&qp,  g_q);
    cudaGetSymbolAddress((void**)&kp,  g_k);
    cudaGetSymbolAddress((void**)&vtp, g_vt);
    cudaGetSymbolAddress((void**)&yp,  g_y);

    const dim3 blk(256);

    // 1) In-projections: [4096,1024] @ W^T + b, scattered into head-major layouts
    {
        dim3 grid(EMB / 128, MROWS / 128, 1);
        gemm_kern<128,128,16,8,8><<<grid, blk>>>(query, q_w, q_b, qp,
            MROWS, EMB, EMB, 0, 0, 0, 1.0f, MODE_QK);
        gemm_kern<128,128,16,8,8><<<grid, blk>>>(key_i, k_w, k_b, kp,
            MROWS, EMB, EMB, 0, 0, 0, 1.0f, MODE_QK);
        gemm_kern<128,128,16,8,8><<<grid, blk>>>(value, v_w, v_b, vtp,
            MROWS, EMB, EMB, 0, 0, 0, 1.0f, MODE_VT);
    }

    // 2) Logits: per (b,h)  Q[2048,64] @ K[2048,64]^T * (1/8) -> attn region
    {
        dim3 grid(S_LEN / 128, S_LEN / 128, BATCH * HEADS);
        gemm_kern<128,128,16,8,8><<<grid, blk>>>(qp, kp, nullptr, attn,
            S_LEN, S_LEN, HDIM,
            (size_t)S_LEN * HDIM, (size_t)S_LEN * HDIM, (size_t)S_LEN * S_LEN,
            0.125f, MODE_PLAIN);
    }

    // 3) Row softmax in place on the attention output
    softmax_rows<<<BATCH * HEADS * S_LEN, blk>>>(attn);

    // 4) AV: per (b,h)  A[2048,2048] @ Vt[64,2048]^T -> y [B,S,H,Hd]
    {
        dim3 grid(HDIM / 64, S_LEN / 128, BATCH * HEADS);
        gemm_kern<128,64,16,8,4><<<grid, blk>>>(attn, vtp, nullptr, yp,
            S_LEN, HDIM, S_LEN,
            (size_t)S_LEN * S_LEN, (size_t)HDIM * S_LEN, 0,
            1.0f, MODE_AV);
    }

    // 5) Output projection: y[4096,1024] @ o_w^T + o_b -> out
    {
        dim3 grid(EMB / 128, MROWS / 128, 1);
        gemm_kern<128,128,16,8,8><<<grid, blk>>>(yp, o_w, o_b, out,
            MROWS, EMB, EMB, 0, 0, 0, 1.0f, MODE_PLAIN);
    }

    (void)in_sizes; (void)n_in; (void)out_size;
}